// round 1
// baseline (speedup 1.0000x reference)
#include <cuda_runtime.h>
#include <math.h>

// Problem constants
constexpr int Bsz = 4;
constexpr int S   = 2048;
constexpr int E   = 1024;
constexpr int D   = 1024;   // QD == VD

// Scratch (allocation-free: __device__ globals)
__device__ float g_q[(size_t)Bsz * S * D];          // 32 MB
__device__ float g_k[(size_t)Bsz * S * D];          // 32 MB
__device__ float g_v[(size_t)Bsz * S * D];          // 32 MB
__device__ float g_p[(size_t)Bsz * S * S];          // 64 MB (scores -> probs)

#define BM 128
#define BN 128
#define BK 8
#define TM 8
#define TN 8
#define NTHREADS 256

// ---------------------------------------------------------------------------
// Kernel 1: QKV projections.  out[z] = x @ W[z] + b[z]
// x: [B*S, E] row-major; W: [E, D] row-major.
// grid: (D/BN, B*S/BM, 3)
// ---------------------------------------------------------------------------
__global__ __launch_bounds__(NTHREADS) void qkv_kernel(
    const float* __restrict__ x,
    const float* __restrict__ Wq, const float* __restrict__ bq,
    const float* __restrict__ Wk, const float* __restrict__ bk,
    const float* __restrict__ Wv, const float* __restrict__ bv)
{
    const float* W;
    const float* bias;
    float* out;
    if (blockIdx.z == 0)      { W = Wq; bias = bq; out = g_q; }
    else if (blockIdx.z == 1) { W = Wk; bias = bk; out = g_k; }
    else                      { W = Wv; bias = bv; out = g_v; }

    __shared__ float As[BK][BM];
    __shared__ float Bs[BK][BN];

    const int tid = threadIdx.x;
    const int tx = tid % 16;
    const int ty = tid / 16;
    const int row0 = blockIdx.y * BM;
    const int col0 = blockIdx.x * BN;

    float acc[TM][TN];
#pragma unroll
    for (int i = 0; i < TM; i++)
#pragma unroll
        for (int j = 0; j < TN; j++) acc[i][j] = 0.0f;

    for (int k0 = 0; k0 < E; k0 += BK) {
        // A tile: BM x BK  (x rows)
#pragma unroll
        for (int i = 0; i < 4; i++) {
            int idx = tid + i * NTHREADS;       // 0..1023
            int r = idx / BK, c = idx % BK;
            As[c][r] = x[(size_t)(row0 + r) * E + (k0 + c)];
        }
        // B tile: BK x BN  (W rows)
#pragma unroll
        for (int i = 0; i < 4; i++) {
            int idx = tid + i * NTHREADS;
            int r = idx / BN, c = idx % BN;
            Bs[r][c] = W[(size_t)(k0 + r) * D + (col0 + c)];
        }
        __syncthreads();

#pragma unroll
        for (int kk = 0; kk < BK; kk++) {
            float ar[TM], br[TN];
#pragma unroll
            for (int i = 0; i < TM; i++) ar[i] = As[kk][ty * TM + i];
#pragma unroll
            for (int j = 0; j < TN; j++) br[j] = Bs[kk][tx * TN + j];
#pragma unroll
            for (int i = 0; i < TM; i++)
#pragma unroll
                for (int j = 0; j < TN; j++) acc[i][j] += ar[i] * br[j];
        }
        __syncthreads();
    }

#pragma unroll
    for (int i = 0; i < TM; i++) {
        int m = row0 + ty * TM + i;
#pragma unroll
        for (int j = 0; j < TN; j++) {
            int n = col0 + tx * TN + j;
            out[(size_t)m * D + n] = acc[i][j] + bias[n];
        }
    }
}

// ---------------------------------------------------------------------------
// Kernel 2: scores = Q @ K^T / D, masked.  grid: (S/BN, S/BM, B)
// ---------------------------------------------------------------------------
__global__ __launch_bounds__(NTHREADS) void scores_kernel(const int* __restrict__ mask)
{
    const int b = blockIdx.z;
    const float* Q = g_q + (size_t)b * S * D;
    const float* K = g_k + (size_t)b * S * D;

    __shared__ float As[BK][BM];
    __shared__ float Bs[BK][BN];

    const int tid = threadIdx.x;
    const int tx = tid % 16;
    const int ty = tid / 16;
    const int row0 = blockIdx.y * BM;   // query rows
    const int col0 = blockIdx.x * BN;   // key rows

    float acc[TM][TN];
#pragma unroll
    for (int i = 0; i < TM; i++)
#pragma unroll
        for (int j = 0; j < TN; j++) acc[i][j] = 0.0f;

    for (int k0 = 0; k0 < D; k0 += BK) {
#pragma unroll
        for (int i = 0; i < 4; i++) {
            int idx = tid + i * NTHREADS;
            int r = idx / BK, c = idx % BK;
            As[c][r] = Q[(size_t)(row0 + r) * D + (k0 + c)];
        }
#pragma unroll
        for (int i = 0; i < 4; i++) {
            int idx = tid + i * NTHREADS;
            int r = idx / BK, c = idx % BK;   // same layout: K rows
            Bs[c][r] = K[(size_t)(col0 + r) * D + (k0 + c)];
        }
        __syncthreads();

#pragma unroll
        for (int kk = 0; kk < BK; kk++) {
            float ar[TM], br[TN];
#pragma unroll
            for (int i = 0; i < TM; i++) ar[i] = As[kk][ty * TM + i];
#pragma unroll
            for (int j = 0; j < TN; j++) br[j] = Bs[kk][tx * TN + j];
#pragma unroll
            for (int i = 0; i < TM; i++)
#pragma unroll
                for (int j = 0; j < TN; j++) acc[i][j] += ar[i] * br[j];
        }
        __syncthreads();
    }

    const float inv_d = 1.0f / (float)D;
    float* P = g_p + (size_t)b * S * S;
    const int* Mrow = mask + (size_t)b * S * S;
#pragma unroll
    for (int i = 0; i < TM; i++) {
        int m = row0 + ty * TM + i;
#pragma unroll
        for (int j = 0; j < TN; j++) {
            int n = col0 + tx * TN + j;
            int mk = Mrow[(size_t)m * S + n];
            P[(size_t)m * S + n] = (mk == 0) ? -INFINITY : acc[i][j] * inv_d;
        }
    }
}

// ---------------------------------------------------------------------------
// Kernel 3: row softmax over g_p.  grid: (S, B), block: 256
// ---------------------------------------------------------------------------
__global__ __launch_bounds__(NTHREADS) void softmax_kernel()
{
    const int b = blockIdx.y;
    const int q = blockIdx.x;
    float* row = g_p + ((size_t)b * S + q) * S;
    const int tid = threadIdx.x;

    __shared__ float red[NTHREADS];

    // pass 1: max
    float lmax = -INFINITY;
    for (int i = tid; i < S; i += NTHREADS) lmax = fmaxf(lmax, row[i]);
    red[tid] = lmax;
    __syncthreads();
    for (int s = NTHREADS / 2; s > 0; s >>= 1) {
        if (tid < s) red[tid] = fmaxf(red[tid], red[tid + s]);
        __syncthreads();
    }
    const float m = red[0];
    __syncthreads();

    // pass 2: exp + sum
    float lsum = 0.0f;
    for (int i = tid; i < S; i += NTHREADS) {
        float e = expf(row[i] - m);
        row[i] = e;
        lsum += e;
    }
    red[tid] = lsum;
    __syncthreads();
    for (int s = NTHREADS / 2; s > 0; s >>= 1) {
        if (tid < s) red[tid] += red[tid + s];
        __syncthreads();
    }
    const float inv = 1.0f / red[0];
    __syncthreads();

    // pass 3: normalize
    for (int i = tid; i < S; i += NTHREADS) row[i] *= inv;
}

// ---------------------------------------------------------------------------
// Kernel 4: out = P @ V.  grid: (D/BN, S/BM, B)
// ---------------------------------------------------------------------------
__global__ __launch_bounds__(NTHREADS) void pv_kernel(float* __restrict__ out)
{
    const int b = blockIdx.z;
    const float* P = g_p + (size_t)b * S * S;
    const float* V = g_v + (size_t)b * S * D;
    float* O = out + (size_t)b * S * D;

    __shared__ float As[BK][BM];
    __shared__ float Bs[BK][BN];

    const int tid = threadIdx.x;
    const int tx = tid % 16;
    const int ty = tid / 16;
    const int row0 = blockIdx.y * BM;
    const int col0 = blockIdx.x * BN;

    float acc[TM][TN];
#pragma unroll
    for (int i = 0; i < TM; i++)
#pragma unroll
        for (int j = 0; j < TN; j++) acc[i][j] = 0.0f;

    for (int k0 = 0; k0 < S; k0 += BK) {
#pragma unroll
        for (int i = 0; i < 4; i++) {
            int idx = tid + i * NTHREADS;
            int r = idx / BK, c = idx % BK;
            As[c][r] = P[(size_t)(row0 + r) * S + (k0 + c)];
        }
#pragma unroll
        for (int i = 0; i < 4; i++) {
            int idx = tid + i * NTHREADS;
            int r = idx / BN, c = idx % BN;
            Bs[r][c] = V[(size_t)(k0 + r) * D + (col0 + c)];
        }
        __syncthreads();

#pragma unroll
        for (int kk = 0; kk < BK; kk++) {
            float ar[TM], br[TN];
#pragma unroll
            for (int i = 0; i < TM; i++) ar[i] = As[kk][ty * TM + i];
#pragma unroll
            for (int j = 0; j < TN; j++) br[j] = Bs[kk][tx * TN + j];
#pragma unroll
            for (int i = 0; i < TM; i++)
#pragma unroll
                for (int j = 0; j < TN; j++) acc[i][j] += ar[i] * br[j];
        }
        __syncthreads();
    }

#pragma unroll
    for (int i = 0; i < TM; i++) {
        int m = row0 + ty * TM + i;
#pragma unroll
        for (int j = 0; j < TN; j++) {
            int n = col0 + tx * TN + j;
            O[(size_t)m * D + n] = acc[i][j];
        }
    }
}

// ---------------------------------------------------------------------------
extern "C" void kernel_launch(void* const* d_in, const int* in_sizes, int n_in,
                              void* d_out, int out_size)
{
    const float* x    = (const float*)d_in[0];
    const int*   mask = (const int*)  d_in[1];
    const float* Wq   = (const float*)d_in[2];
    const float* bq   = (const float*)d_in[3];
    const float* Wk   = (const float*)d_in[4];
    const float* bk   = (const float*)d_in[5];
    const float* Wv   = (const float*)d_in[6];
    const float* bv   = (const float*)d_in[7];
    float* out = (float*)d_out;

    dim3 blk(NTHREADS);

    qkv_kernel<<<dim3(D / BN, (Bsz * S) / BM, 3), blk>>>(x, Wq, bq, Wk, bk, Wv, bv);
    scores_kernel<<<dim3(S / BN, S / BM, Bsz), blk>>>(mask);
    softmax_kernel<<<dim3(S, Bsz), blk>>>();
    pv_kernel<<<dim3(D / BN, S / BM, Bsz), blk>>>(out);
}

// round 3
// speedup vs baseline: 3.3691x; 3.3691x over previous
#include <cuda_runtime.h>
#include <cuda_bf16.h>
#include <cstdint>
#include <math.h>

// ───────────────────────── problem constants ─────────────────────────
constexpr int Bsz = 4, S = 2048, E = 1024, D = 1024;

// ───────────────────────── device scratch (no allocs) ────────────────
__device__ __nv_bfloat16 g_xh[(size_t)Bsz * S * E];
__device__ __nv_bfloat16 g_xl[(size_t)Bsz * S * E];
__device__ __nv_bfloat16 g_Wh[(size_t)3 * E * D];   // [z][n][k] (transposed)
__device__ __nv_bfloat16 g_Wl[(size_t)3 * E * D];
__device__ __nv_bfloat16 g_qh[(size_t)Bsz * S * D];
__device__ __nv_bfloat16 g_ql[(size_t)Bsz * S * D];
__device__ __nv_bfloat16 g_kh[(size_t)Bsz * S * D];
__device__ __nv_bfloat16 g_kl[(size_t)Bsz * S * D];
__device__ __nv_bfloat16 g_vh[(size_t)Bsz * D * S]; // [b][d][s] (V transposed)
__device__ __nv_bfloat16 g_vl[(size_t)Bsz * D * S];
__device__ float         g_sc[(size_t)Bsz * S * S]; // masked scaled scores
__device__ __nv_bfloat16 g_ph[(size_t)Bsz * S * S]; // probs hi/lo
__device__ __nv_bfloat16 g_pl[(size_t)Bsz * S * S];

// ───────────────────────── tile config ───────────────────────────────
constexpr int BM = 128, BN = 128, BK = 32, NTH = 256, NSTAGE = 4;
constexpr int RS_B = 80;                         // smem row stride in bytes (32 bf16 + pad)
constexpr int PLANE_B = 128 * RS_B;              // 10240 B per operand plane
constexpr int STAGE_B = 4 * PLANE_B;             // Ah, Al, Bh, Bl
constexpr int SMEM_TOTAL = NSTAGE * STAGE_B;     // 163840 B

// ───────────────────────── PTX helpers ───────────────────────────────
__device__ __forceinline__ uint32_t s2u(const void* p) {
    uint32_t a;
    asm("{ .reg .u64 t; cvta.to.shared.u64 t, %1; cvt.u32.u64 %0, t; }" : "=r"(a) : "l"(p));
    return a;
}
__device__ __forceinline__ void cp_async16(uint32_t dst, const void* src) {
    asm volatile("cp.async.ca.shared.global [%0], [%1], 16;" :: "r"(dst), "l"(src) : "memory");
}
__device__ __forceinline__ void cp_commit() {
    asm volatile("cp.async.commit_group;" ::: "memory");
}
__device__ __forceinline__ void cp_wait2() {
    asm volatile("cp.async.wait_group 2;" ::: "memory");
}
__device__ __forceinline__ void ldmatrix4(uint32_t* r, uint32_t addr) {
    asm volatile("ldmatrix.sync.aligned.m8n8.x4.shared.b16 {%0,%1,%2,%3}, [%4];"
                 : "=r"(r[0]), "=r"(r[1]), "=r"(r[2]), "=r"(r[3]) : "r"(addr));
}
__device__ __forceinline__ void ldmatrix2(uint32_t* r, uint32_t addr) {
    asm volatile("ldmatrix.sync.aligned.m8n8.x2.shared.b16 {%0,%1}, [%2];"
                 : "=r"(r[0]), "=r"(r[1]) : "r"(addr));
}
__device__ __forceinline__ void mma16816(float* c, const uint32_t* a, const uint32_t* b) {
    asm volatile(
        "mma.sync.aligned.m16n8k16.row.col.f32.bf16.bf16.f32 "
        "{%0,%1,%2,%3}, {%4,%5,%6,%7}, {%8,%9}, {%0,%1,%2,%3};"
        : "+f"(c[0]), "+f"(c[1]), "+f"(c[2]), "+f"(c[3])
        : "r"(a[0]), "r"(a[1]), "r"(a[2]), "r"(a[3]), "r"(b[0]), "r"(b[1]));
}
__device__ __forceinline__ void split2(float v, __nv_bfloat16& h, __nv_bfloat16& l) {
    h = __float2bfloat16(v);
    l = __float2bfloat16(v - __bfloat162float(h));
}

// ───────────────────────── GEMM ──────────────────────────────────────
// C[m][n] = sum_k A[m][k] * B[n][k], bf16x3 split (AhBh + AhBl + AlBh).
// OP: 0=Q proj, 1=K proj, 2=V proj (transposed output), 3=scores, 4=PV
template <int OP>
__global__ __launch_bounds__(NTH, 1) void gemm_kernel(
    const float* __restrict__ bias,
    const int*   __restrict__ mask,
    float*       __restrict__ outF)
{
    extern __shared__ char smem[];
    const uint32_t sbase = s2u(smem);
    const int tid = threadIdx.x;
    const int wid = tid >> 5, lane = tid & 31;
    const size_t z = blockIdx.z;

    // operand binding
    const __nv_bfloat16 *Ah, *Al, *Bh, *Bl;
    int Kdim;
    if (OP == 0) { Ah = g_xh; Al = g_xl; Bh = g_Wh; Bl = g_Wl; Kdim = E; }
    else if (OP == 1) { Ah = g_xh; Al = g_xl; Bh = g_Wh + (size_t)E * D; Bl = g_Wl + (size_t)E * D; Kdim = E; }
    else if (OP == 2) { Ah = g_Wh + (size_t)2 * E * D; Al = g_Wl + (size_t)2 * E * D; Bh = g_xh; Bl = g_xl; Kdim = E; }
    else if (OP == 3) { Ah = g_qh + z * (size_t)S * D; Al = g_ql + z * (size_t)S * D;
                        Bh = g_kh + z * (size_t)S * D; Bl = g_kl + z * (size_t)S * D; Kdim = D; }
    else              { Ah = g_ph + z * (size_t)S * S; Al = g_pl + z * (size_t)S * S;
                        Bh = g_vh + z * (size_t)D * S; Bl = g_vl + z * (size_t)D * S; Kdim = S; }

    const int row0 = blockIdx.y * BM;
    const int col0 = blockIdx.x * BN;
    const int NC = Kdim / BK;

    auto load_stage = [&](int c, int st) {
        const int k0 = c * BK;
        const uint32_t stb = sbase + (uint32_t)st * STAGE_B;
#pragma unroll
        for (int j = 0; j < 8; j++) {
            const int pl = j >> 1;
            const int idx = ((j & 1) << 8) + tid;    // 0..511
            const int r = idx >> 2, u = idx & 3;
            const __nv_bfloat16* src;
            if (pl == 0)      src = Ah + (size_t)(row0 + r) * Kdim;
            else if (pl == 1) src = Al + (size_t)(row0 + r) * Kdim;
            else if (pl == 2) src = Bh + (size_t)(col0 + r) * Kdim;
            else              src = Bl + (size_t)(col0 + r) * Kdim;
            src += k0 + u * 8;
            cp_async16(stb + pl * PLANE_B + r * RS_B + u * 16, src);
        }
    };

    float acc[4][4][4];
#pragma unroll
    for (int i = 0; i < 4; i++)
#pragma unroll
        for (int j = 0; j < 4; j++)
#pragma unroll
            for (int t = 0; t < 4; t++) acc[i][j][t] = 0.0f;

    // prologue: NSTAGE-1 chunks in flight
#pragma unroll
    for (int s = 0; s < NSTAGE - 1; s++) { load_stage(s, s); cp_commit(); }

    const int wm = (wid & 1) * 64;    // warp m-offset (2 warps in m)
    const int wn = (wid >> 1) * 32;   // warp n-offset (4 warps in n)

    for (int c = 0; c < NC; c++) {
        cp_wait2();
        __syncthreads();

        const uint32_t stb = sbase + (uint32_t)(c % NSTAGE) * STAGE_B;
        const uint32_t sAh = stb, sAl = stb + PLANE_B;
        const uint32_t sBh = stb + 2 * PLANE_B, sBl = stb + 3 * PLANE_B;

#pragma unroll
        for (int ks = 0; ks < 2; ks++) {
            uint32_t ah[4][4], al[4][4], bh[4][2], bl[4][2];
            const int arow = wm + (lane & 15);
            const int akb = (ks * 16 + (lane >> 4) * 8) * 2;
#pragma unroll
            for (int i = 0; i < 4; i++) {
                ldmatrix4(ah[i], sAh + (arow + i * 16) * RS_B + akb);
                ldmatrix4(al[i], sAl + (arow + i * 16) * RS_B + akb);
            }
            const int brow = wn + (lane & 7);
            const int bkb = (ks * 16 + ((lane >> 3) & 1) * 8) * 2;
#pragma unroll
            for (int j = 0; j < 4; j++) {
                ldmatrix2(bh[j], sBh + (brow + j * 8) * RS_B + bkb);
                ldmatrix2(bl[j], sBl + (brow + j * 8) * RS_B + bkb);
            }
#pragma unroll
            for (int i = 0; i < 4; i++)
#pragma unroll
                for (int j = 0; j < 4; j++) {
                    mma16816(acc[i][j], ah[i], bh[j]);
                    mma16816(acc[i][j], ah[i], bl[j]);
                    mma16816(acc[i][j], al[i], bh[j]);
                }
        }

        if (c + NSTAGE - 1 < NC) load_stage(c + NSTAGE - 1, (c + NSTAGE - 1) % NSTAGE);
        cp_commit();
    }

    // ───────── epilogue ─────────
    __nv_bfloat16 *oH = nullptr, *oL = nullptr;
    if (OP == 0) { oH = g_qh; oL = g_ql; }
    else if (OP == 1) { oH = g_kh; oL = g_kl; }
    else if (OP == 2) { oH = g_vh; oL = g_vl; }

#pragma unroll
    for (int i = 0; i < 4; i++) {
        const int m = row0 + wm + i * 16 + (lane >> 2);
        float bm0 = 0.0f, bm1 = 0.0f;
        if (OP == 2) { bm0 = bias[m]; bm1 = bias[m + 8]; }
#pragma unroll
        for (int j = 0; j < 4; j++) {
            const int n = col0 + wn + j * 8 + 2 * (lane & 3);
            float v00 = acc[i][j][0], v01 = acc[i][j][1];   // row m,   cols n, n+1
            float v10 = acc[i][j][2], v11 = acc[i][j][3];   // row m+8, cols n, n+1

            if (OP == 0 || OP == 1) {
                float2 bb = *reinterpret_cast<const float2*>(bias + n);
                v00 += bb.x; v01 += bb.y; v10 += bb.x; v11 += bb.y;
                __nv_bfloat16 h0, l0, h1, l1;
                __nv_bfloat162 hv, lv;
                split2(v00, h0, l0); split2(v01, h1, l1);
                hv.x = h0; hv.y = h1; lv.x = l0; lv.y = l1;
                *reinterpret_cast<__nv_bfloat162*>(oH + (size_t)m * D + n) = hv;
                *reinterpret_cast<__nv_bfloat162*>(oL + (size_t)m * D + n) = lv;
                split2(v10, h0, l0); split2(v11, h1, l1);
                hv.x = h0; hv.y = h1; lv.x = l0; lv.y = l1;
                *reinterpret_cast<__nv_bfloat162*>(oH + (size_t)(m + 8) * D + n) = hv;
                *reinterpret_cast<__nv_bfloat162*>(oL + (size_t)(m + 8) * D + n) = lv;
            } else if (OP == 2) {
                // m = d index, n = global token: out[b][d][s]
                const int b = n >> 11, sI = n & 2047;
                const size_t base = (size_t)b * D * S + (size_t)m * S + sI;
                v00 += bm0; v01 += bm0; v10 += bm1; v11 += bm1;
                __nv_bfloat16 h0, l0, h1, l1;
                __nv_bfloat162 hv, lv;
                split2(v00, h0, l0); split2(v01, h1, l1);
                hv.x = h0; hv.y = h1; lv.x = l0; lv.y = l1;
                *reinterpret_cast<__nv_bfloat162*>(oH + base) = hv;
                *reinterpret_cast<__nv_bfloat162*>(oL + base) = lv;
                split2(v10, h0, l0); split2(v11, h1, l1);
                hv.x = h0; hv.y = h1; lv.x = l0; lv.y = l1;
                *reinterpret_cast<__nv_bfloat162*>(oH + base + 8 * S) = hv;
                *reinterpret_cast<__nv_bfloat162*>(oL + base + 8 * S) = lv;
            } else if (OP == 3) {
                const float sc = 1.0f / 1024.0f;
                const int* mrow = mask + z * (size_t)S * S;
                float* orow = g_sc + z * (size_t)S * S;
                int2 mk = *reinterpret_cast<const int2*>(mrow + (size_t)m * S + n);
                float2 o;
                o.x = (mk.x == 0) ? -INFINITY : v00 * sc;
                o.y = (mk.y == 0) ? -INFINITY : v01 * sc;
                *reinterpret_cast<float2*>(orow + (size_t)m * S + n) = o;
                mk = *reinterpret_cast<const int2*>(mrow + (size_t)(m + 8) * S + n);
                o.x = (mk.x == 0) ? -INFINITY : v10 * sc;
                o.y = (mk.y == 0) ? -INFINITY : v11 * sc;
                *reinterpret_cast<float2*>(orow + (size_t)(m + 8) * S + n) = o;
            } else {
                float* O = outF + z * (size_t)S * D;
                float2 o;
                o.x = v00; o.y = v01;
                *reinterpret_cast<float2*>(O + (size_t)m * D + n) = o;
                o.x = v10; o.y = v11;
                *reinterpret_cast<float2*>(O + (size_t)(m + 8) * D + n) = o;
            }
        }
    }
}

// ───────────────────────── conversion kernels ────────────────────────
__global__ __launch_bounds__(256) void convert_x_kernel(const float* __restrict__ x) {
    size_t i4 = (size_t)blockIdx.x * 256 + threadIdx.x;
    float4 v = reinterpret_cast<const float4*>(x)[i4];
    __nv_bfloat16 h0, l0, h1, l1, h2, l2, h3, l3;
    split2(v.x, h0, l0); split2(v.y, h1, l1);
    split2(v.z, h2, l2); split2(v.w, h3, l3);
    __nv_bfloat162* oh = reinterpret_cast<__nv_bfloat162*>(g_xh) + i4 * 2;
    __nv_bfloat162* ol = reinterpret_cast<__nv_bfloat162*>(g_xl) + i4 * 2;
    __nv_bfloat162 a, b;
    a.x = h0; a.y = h1; b.x = h2; b.y = h3;
    oh[0] = a; oh[1] = b;
    a.x = l0; a.y = l1; b.x = l2; b.y = l3;
    ol[0] = a; ol[1] = b;
}

// W [E][D] row-major -> planes [z][n][k] (transposed)
__global__ __launch_bounds__(256) void convert_w_kernel(
    const float* __restrict__ Wq, const float* __restrict__ Wk, const float* __restrict__ Wv)
{
    const float* W = (blockIdx.z == 0) ? Wq : (blockIdx.z == 1) ? Wk : Wv;
    __nv_bfloat16* oh = g_Wh + (size_t)blockIdx.z * E * D;
    __nv_bfloat16* ol = g_Wl + (size_t)blockIdx.z * E * D;

    __shared__ float t[32][33];
    const int tx = threadIdx.x & 31, ty = threadIdx.x >> 5;   // 32 x 8
#pragma unroll
    for (int i = 0; i < 4; i++) {
        int kk = blockIdx.y * 32 + ty + i * 8;
        t[ty + i * 8][tx] = W[(size_t)kk * D + blockIdx.x * 32 + tx];
    }
    __syncthreads();
#pragma unroll
    for (int i = 0; i < 4; i++) {
        int n  = blockIdx.x * 32 + ty + i * 8;
        int kk = blockIdx.y * 32 + tx;
        float v = t[tx][ty + i * 8];
        __nv_bfloat16 h, l;
        split2(v, h, l);
        oh[(size_t)n * E + kk] = h;
        ol[(size_t)n * E + kk] = l;
    }
}

// ───────────────────────── softmax ───────────────────────────────────
__global__ __launch_bounds__(256) void softmax_kernel() {
    const int b = blockIdx.y, q = blockIdx.x;
    const float* row = g_sc + ((size_t)b * S + q) * S;
    __nv_bfloat16* oh = g_ph + ((size_t)b * S + q) * S;
    __nv_bfloat16* ol = g_pl + ((size_t)b * S + q) * S;
    const int tid = threadIdx.x;

    __shared__ float red[256];

    float vals[8];
#pragma unroll
    for (int i = 0; i < 8; i++) vals[i] = row[tid + i * 256];

    float lmax = -INFINITY;
#pragma unroll
    for (int i = 0; i < 8; i++) lmax = fmaxf(lmax, vals[i]);
    red[tid] = lmax;
    __syncthreads();
    for (int st = 128; st > 0; st >>= 1) {
        if (tid < st) red[tid] = fmaxf(red[tid], red[tid + st]);
        __syncthreads();
    }
    const float mx = red[0];
    __syncthreads();

    float lsum = 0.0f;
#pragma unroll
    for (int i = 0; i < 8; i++) { vals[i] = expf(vals[i] - mx); lsum += vals[i]; }
    red[tid] = lsum;
    __syncthreads();
    for (int st = 128; st > 0; st >>= 1) {
        if (tid < st) red[tid] += red[tid + st];
        __syncthreads();
    }
    const float inv = 1.0f / red[0];

#pragma unroll
    for (int i = 0; i < 8; i++) {
        float p = vals[i] * inv;
        __nv_bfloat16 h, l;
        split2(p, h, l);
        oh[tid + i * 256] = h;
        ol[tid + i * 256] = l;
    }
}

// ───────────────────────── host launch ───────────────────────────────
extern "C" void kernel_launch(void* const* d_in, const int* in_sizes, int n_in,
                              void* d_out, int out_size)
{
    const float* x    = (const float*)d_in[0];
    const int*   mask = (const int*)  d_in[1];
    const float* Wq   = (const float*)d_in[2];
    const float* bq   = (const float*)d_in[3];
    const float* Wk   = (const float*)d_in[4];
    const float* bk   = (const float*)d_in[5];
    const float* Wv   = (const float*)d_in[6];
    const float* bv   = (const float*)d_in[7];
    float* out = (float*)d_out;

    cudaFuncSetAttribute(gemm_kernel<0>, cudaFuncAttributeMaxDynamicSharedMemorySize, SMEM_TOTAL);
    cudaFuncSetAttribute(gemm_kernel<1>, cudaFuncAttributeMaxDynamicSharedMemorySize, SMEM_TOTAL);
    cudaFuncSetAttribute(gemm_kernel<2>, cudaFuncAttributeMaxDynamicSharedMemorySize, SMEM_TOTAL);
    cudaFuncSetAttribute(gemm_kernel<3>, cudaFuncAttributeMaxDynamicSharedMemorySize, SMEM_TOTAL);
    cudaFuncSetAttribute(gemm_kernel<4>, cudaFuncAttributeMaxDynamicSharedMemorySize, SMEM_TOTAL);

    // 1) fp32 -> hi/lo bf16 planes
    convert_x_kernel<<<(unsigned)((size_t)Bsz * S * E / 4 / 256), 256>>>(x);
    convert_w_kernel<<<dim3(D / 32, E / 32, 3), 256>>>(Wq, Wk, Wv);

    // 2) projections: Q, K ([token][d]), V (transposed, [b][d][s])
    gemm_kernel<0><<<dim3(D / BN, (Bsz * S) / BM, 1), NTH, SMEM_TOTAL>>>(bq, nullptr, nullptr);
    gemm_kernel<1><<<dim3(D / BN, (Bsz * S) / BM, 1), NTH, SMEM_TOTAL>>>(bk, nullptr, nullptr);
    gemm_kernel<2><<<dim3((Bsz * S) / BN, D / BM, 1), NTH, SMEM_TOTAL>>>(bv, nullptr, nullptr);

    // 3) scores = QK^T / 1024, masked
    gemm_kernel<3><<<dim3(S / BN, S / BM, Bsz), NTH, SMEM_TOTAL>>>(nullptr, mask, nullptr);

    // 4) softmax -> prob planes
    softmax_kernel<<<dim3(S, Bsz), 256>>>();

    // 5) out = P @ V
    gemm_kernel<4><<<dim3(D / BN, S / BM, Bsz), NTH, SMEM_TOTAL>>>(nullptr, nullptr, out);
}

// round 4
// speedup vs baseline: 3.3707x; 1.0005x over previous
#include <cuda_runtime.h>
#include <cuda_bf16.h>
#include <cstdint>
#include <math.h>

// ───────────────────────── problem constants ─────────────────────────
constexpr int Bsz = 4, S = 2048, E = 1024, D = 1024;

// ───────────────────────── device scratch (no allocs) ────────────────
__device__ __nv_bfloat16 g_xh[(size_t)Bsz * S * E];
__device__ __nv_bfloat16 g_xl[(size_t)Bsz * S * E];
__device__ __nv_bfloat16 g_Wh[(size_t)3 * E * D];   // [z][n][k] (transposed)
__device__ __nv_bfloat16 g_Wl[(size_t)3 * E * D];
__device__ __nv_bfloat16 g_qh[(size_t)Bsz * S * D];
__device__ __nv_bfloat16 g_ql[(size_t)Bsz * S * D];
__device__ __nv_bfloat16 g_kh[(size_t)Bsz * S * D];
__device__ __nv_bfloat16 g_kl[(size_t)Bsz * S * D];
__device__ __nv_bfloat16 g_vh[(size_t)Bsz * D * S]; // [b][d][s] (V transposed)
__device__ __nv_bfloat16 g_vl[(size_t)Bsz * D * S];
__device__ float         g_sc[(size_t)Bsz * S * S]; // masked scaled scores
__device__ __nv_bfloat16 g_ph[(size_t)Bsz * S * S]; // probs hi/lo
__device__ __nv_bfloat16 g_pl[(size_t)Bsz * S * S];

// ───────────────────────── tile config ───────────────────────────────
constexpr int BM = 128, BN = 128, BK = 32, NTH = 256, NSTAGE = 4;
constexpr int RS_B = 80;                         // smem row stride in bytes (32 bf16 + pad)
constexpr int PLANE_B = 128 * RS_B;              // 10240 B per operand plane
constexpr int STAGE_B = 4 * PLANE_B;             // Ah, Al, Bh, Bl
constexpr int SMEM_TOTAL = NSTAGE * STAGE_B;     // 163840 B

// ───────────────────────── PTX helpers ───────────────────────────────
__device__ __forceinline__ uint32_t s2u(const void* p) {
    uint32_t a;
    asm("{ .reg .u64 t; cvta.to.shared.u64 t, %1; cvt.u32.u64 %0, t; }" : "=r"(a) : "l"(p));
    return a;
}
__device__ __forceinline__ void cp_async16(uint32_t dst, const void* src) {
    asm volatile("cp.async.ca.shared.global [%0], [%1], 16;" :: "r"(dst), "l"(src) : "memory");
}
__device__ __forceinline__ void cp_commit() {
    asm volatile("cp.async.commit_group;" ::: "memory");
}
__device__ __forceinline__ void cp_wait2() {
    asm volatile("cp.async.wait_group 2;" ::: "memory");
}
__device__ __forceinline__ void ldmatrix4(uint32_t* r, uint32_t addr) {
    asm volatile("ldmatrix.sync.aligned.m8n8.x4.shared.b16 {%0,%1,%2,%3}, [%4];"
                 : "=r"(r[0]), "=r"(r[1]), "=r"(r[2]), "=r"(r[3]) : "r"(addr));
}
__device__ __forceinline__ void ldmatrix2(uint32_t* r, uint32_t addr) {
    asm volatile("ldmatrix.sync.aligned.m8n8.x2.shared.b16 {%0,%1}, [%2];"
                 : "=r"(r[0]), "=r"(r[1]) : "r"(addr));
}
__device__ __forceinline__ void mma16816(float* c, const uint32_t* a, const uint32_t* b) {
    asm volatile(
        "mma.sync.aligned.m16n8k16.row.col.f32.bf16.bf16.f32 "
        "{%0,%1,%2,%3}, {%4,%5,%6,%7}, {%8,%9}, {%0,%1,%2,%3};"
        : "+f"(c[0]), "+f"(c[1]), "+f"(c[2]), "+f"(c[3])
        : "r"(a[0]), "r"(a[1]), "r"(a[2]), "r"(a[3]), "r"(b[0]), "r"(b[1]));
}
__device__ __forceinline__ void split2(float v, __nv_bfloat16& h, __nv_bfloat16& l) {
    h = __float2bfloat16(v);
    l = __float2bfloat16(v - __bfloat162float(h));
}

// ───────────────────────── GEMM ──────────────────────────────────────
// C[m][n] = sum_k A[m][k] * B[n][k], bf16x3 split (AhBh + AhBl + AlBh).
// OP: 0=Q proj, 1=K proj, 2=V proj (transposed output), 3=scores, 4=PV
template <int OP>
__global__ __launch_bounds__(NTH, 1) void gemm_kernel(
    const float* __restrict__ bias,
    const int*   __restrict__ mask,
    float*       __restrict__ outF)
{
    extern __shared__ char smem[];
    const uint32_t sbase = s2u(smem);
    const int tid = threadIdx.x;
    const int wid = tid >> 5, lane = tid & 31;
    const size_t z = blockIdx.z;

    // operand binding
    const __nv_bfloat16 *Ah, *Al, *Bh, *Bl;
    int Kdim;
    if (OP == 0) { Ah = g_xh; Al = g_xl; Bh = g_Wh; Bl = g_Wl; Kdim = E; }
    else if (OP == 1) { Ah = g_xh; Al = g_xl; Bh = g_Wh + (size_t)E * D; Bl = g_Wl + (size_t)E * D; Kdim = E; }
    else if (OP == 2) { Ah = g_Wh + (size_t)2 * E * D; Al = g_Wl + (size_t)2 * E * D; Bh = g_xh; Bl = g_xl; Kdim = E; }
    else if (OP == 3) { Ah = g_qh + z * (size_t)S * D; Al = g_ql + z * (size_t)S * D;
                        Bh = g_kh + z * (size_t)S * D; Bl = g_kl + z * (size_t)S * D; Kdim = D; }
    else              { Ah = g_ph + z * (size_t)S * S; Al = g_pl + z * (size_t)S * S;
                        Bh = g_vh + z * (size_t)D * S; Bl = g_vl + z * (size_t)D * S; Kdim = S; }

    const int row0 = blockIdx.y * BM;
    const int col0 = blockIdx.x * BN;
    const int NC = Kdim / BK;

    auto load_stage = [&](int c, int st) {
        const int k0 = c * BK;
        const uint32_t stb = sbase + (uint32_t)st * STAGE_B;
#pragma unroll
        for (int j = 0; j < 8; j++) {
            const int pl = j >> 1;
            const int idx = ((j & 1) << 8) + tid;    // 0..511
            const int r = idx >> 2, u = idx & 3;
            const __nv_bfloat16* src;
            if (pl == 0)      src = Ah + (size_t)(row0 + r) * Kdim;
            else if (pl == 1) src = Al + (size_t)(row0 + r) * Kdim;
            else if (pl == 2) src = Bh + (size_t)(col0 + r) * Kdim;
            else              src = Bl + (size_t)(col0 + r) * Kdim;
            src += k0 + u * 8;
            cp_async16(stb + pl * PLANE_B + r * RS_B + u * 16, src);
        }
    };

    float acc[4][4][4];
#pragma unroll
    for (int i = 0; i < 4; i++)
#pragma unroll
        for (int j = 0; j < 4; j++)
#pragma unroll
            for (int t = 0; t < 4; t++) acc[i][j][t] = 0.0f;

    // prologue: NSTAGE-1 chunks in flight
#pragma unroll
    for (int s = 0; s < NSTAGE - 1; s++) { load_stage(s, s); cp_commit(); }

    const int wm = (wid & 1) * 64;    // warp m-offset (2 warps in m)
    const int wn = (wid >> 1) * 32;   // warp n-offset (4 warps in n)

    for (int c = 0; c < NC; c++) {
        cp_wait2();
        __syncthreads();

        const uint32_t stb = sbase + (uint32_t)(c % NSTAGE) * STAGE_B;
        const uint32_t sAh = stb, sAl = stb + PLANE_B;
        const uint32_t sBh = stb + 2 * PLANE_B, sBl = stb + 3 * PLANE_B;

#pragma unroll
        for (int ks = 0; ks < 2; ks++) {
            uint32_t ah[4][4], al[4][4], bh[4][2], bl[4][2];
            const int arow = wm + (lane & 15);
            const int akb = (ks * 16 + (lane >> 4) * 8) * 2;
#pragma unroll
            for (int i = 0; i < 4; i++) {
                ldmatrix4(ah[i], sAh + (arow + i * 16) * RS_B + akb);
                ldmatrix4(al[i], sAl + (arow + i * 16) * RS_B + akb);
            }
            const int brow = wn + (lane & 7);
            const int bkb = (ks * 16 + ((lane >> 3) & 1) * 8) * 2;
#pragma unroll
            for (int j = 0; j < 4; j++) {
                ldmatrix2(bh[j], sBh + (brow + j * 8) * RS_B + bkb);
                ldmatrix2(bl[j], sBl + (brow + j * 8) * RS_B + bkb);
            }
#pragma unroll
            for (int i = 0; i < 4; i++)
#pragma unroll
                for (int j = 0; j < 4; j++) {
                    mma16816(acc[i][j], ah[i], bh[j]);
                    mma16816(acc[i][j], ah[i], bl[j]);
                    mma16816(acc[i][j], al[i], bh[j]);
                }
        }

        if (c + NSTAGE - 1 < NC) load_stage(c + NSTAGE - 1, (c + NSTAGE - 1) % NSTAGE);
        cp_commit();
    }

    // ───────── epilogue ─────────
    __nv_bfloat16 *oH = nullptr, *oL = nullptr;
    if (OP == 0) { oH = g_qh; oL = g_ql; }
    else if (OP == 1) { oH = g_kh; oL = g_kl; }
    else if (OP == 2) { oH = g_vh; oL = g_vl; }

#pragma unroll
    for (int i = 0; i < 4; i++) {
        const int m = row0 + wm + i * 16 + (lane >> 2);
        float bm0 = 0.0f, bm1 = 0.0f;
        if (OP == 2) { bm0 = bias[m]; bm1 = bias[m + 8]; }
#pragma unroll
        for (int j = 0; j < 4; j++) {
            const int n = col0 + wn + j * 8 + 2 * (lane & 3);
            float v00 = acc[i][j][0], v01 = acc[i][j][1];   // row m,   cols n, n+1
            float v10 = acc[i][j][2], v11 = acc[i][j][3];   // row m+8, cols n, n+1

            if (OP == 0 || OP == 1) {
                float2 bb = *reinterpret_cast<const float2*>(bias + n);
                v00 += bb.x; v01 += bb.y; v10 += bb.x; v11 += bb.y;
                __nv_bfloat16 h0, l0, h1, l1;
                __nv_bfloat162 hv, lv;
                split2(v00, h0, l0); split2(v01, h1, l1);
                hv.x = h0; hv.y = h1; lv.x = l0; lv.y = l1;
                *reinterpret_cast<__nv_bfloat162*>(oH + (size_t)m * D + n) = hv;
                *reinterpret_cast<__nv_bfloat162*>(oL + (size_t)m * D + n) = lv;
                split2(v10, h0, l0); split2(v11, h1, l1);
                hv.x = h0; hv.y = h1; lv.x = l0; lv.y = l1;
                *reinterpret_cast<__nv_bfloat162*>(oH + (size_t)(m + 8) * D + n) = hv;
                *reinterpret_cast<__nv_bfloat162*>(oL + (size_t)(m + 8) * D + n) = lv;
            } else if (OP == 2) {
                // m = d index, n = global token: out[b][d][s]
                const int b = n >> 11, sI = n & 2047;
                const size_t base = (size_t)b * D * S + (size_t)m * S + sI;
                v00 += bm0; v01 += bm0; v10 += bm1; v11 += bm1;
                __nv_bfloat16 h0, l0, h1, l1;
                __nv_bfloat162 hv, lv;
                split2(v00, h0, l0); split2(v01, h1, l1);
                hv.x = h0; hv.y = h1; lv.x = l0; lv.y = l1;
                *reinterpret_cast<__nv_bfloat162*>(oH + base) = hv;
                *reinterpret_cast<__nv_bfloat162*>(oL + base) = lv;
                split2(v10, h0, l0); split2(v11, h1, l1);
                hv.x = h0; hv.y = h1; lv.x = l0; lv.y = l1;
                *reinterpret_cast<__nv_bfloat162*>(oH + base + 8 * S) = hv;
                *reinterpret_cast<__nv_bfloat162*>(oL + base + 8 * S) = lv;
            } else if (OP == 3) {
                const float sc = 1.0f / 1024.0f;
                const int* mrow = mask + z * (size_t)S * S;
                float* orow = g_sc + z * (size_t)S * S;
                int2 mk = *reinterpret_cast<const int2*>(mrow + (size_t)m * S + n);
                float2 o;
                o.x = (mk.x == 0) ? -INFINITY : v00 * sc;
                o.y = (mk.y == 0) ? -INFINITY : v01 * sc;
                *reinterpret_cast<float2*>(orow + (size_t)m * S + n) = o;
                mk = *reinterpret_cast<const int2*>(mrow + (size_t)(m + 8) * S + n);
                o.x = (mk.x == 0) ? -INFINITY : v10 * sc;
                o.y = (mk.y == 0) ? -INFINITY : v11 * sc;
                *reinterpret_cast<float2*>(orow + (size_t)(m + 8) * S + n) = o;
            } else {
                float* O = outF + z * (size_t)S * D;
                float2 o;
                o.x = v00; o.y = v01;
                *reinterpret_cast<float2*>(O + (size_t)m * D + n) = o;
                o.x = v10; o.y = v11;
                *reinterpret_cast<float2*>(O + (size_t)(m + 8) * D + n) = o;
            }
        }
    }
}

// ───────────────────────── conversion kernels ────────────────────────
__global__ __launch_bounds__(256) void convert_x_kernel(const float* __restrict__ x) {
    size_t i4 = (size_t)blockIdx.x * 256 + threadIdx.x;
    float4 v = reinterpret_cast<const float4*>(x)[i4];
    __nv_bfloat16 h0, l0, h1, l1, h2, l2, h3, l3;
    split2(v.x, h0, l0); split2(v.y, h1, l1);
    split2(v.z, h2, l2); split2(v.w, h3, l3);
    __nv_bfloat162* oh = reinterpret_cast<__nv_bfloat162*>(g_xh) + i4 * 2;
    __nv_bfloat162* ol = reinterpret_cast<__nv_bfloat162*>(g_xl) + i4 * 2;
    __nv_bfloat162 a, b;
    a.x = h0; a.y = h1; b.x = h2; b.y = h3;
    oh[0] = a; oh[1] = b;
    a.x = l0; a.y = l1; b.x = l2; b.y = l3;
    ol[0] = a; ol[1] = b;
}

// W [E][D] row-major -> planes [z][n][k] (transposed)
__global__ __launch_bounds__(256) void convert_w_kernel(
    const float* __restrict__ Wq, const float* __restrict__ Wk, const float* __restrict__ Wv)
{
    const float* W = (blockIdx.z == 0) ? Wq : (blockIdx.z == 1) ? Wk : Wv;
    __nv_bfloat16* oh = g_Wh + (size_t)blockIdx.z * E * D;
    __nv_bfloat16* ol = g_Wl + (size_t)blockIdx.z * E * D;

    __shared__ float t[32][33];
    const int tx = threadIdx.x & 31, ty = threadIdx.x >> 5;   // 32 x 8
#pragma unroll
    for (int i = 0; i < 4; i++) {
        int kk = blockIdx.y * 32 + ty + i * 8;
        t[ty + i * 8][tx] = W[(size_t)kk * D + blockIdx.x * 32 + tx];
    }
    __syncthreads();
#pragma unroll
    for (int i = 0; i < 4; i++) {
        int n  = blockIdx.x * 32 + ty + i * 8;
        int kk = blockIdx.y * 32 + tx;
        float v = t[tx][ty + i * 8];
        __nv_bfloat16 h, l;
        split2(v, h, l);
        oh[(size_t)n * E + kk] = h;
        ol[(size_t)n * E + kk] = l;
    }
}

// ───────────────────────── softmax ───────────────────────────────────
__global__ __launch_bounds__(256) void softmax_kernel() {
    const int b = blockIdx.y, q = blockIdx.x;
    const float* row = g_sc + ((size_t)b * S + q) * S;
    __nv_bfloat16* oh = g_ph + ((size_t)b * S + q) * S;
    __nv_bfloat16* ol = g_pl + ((size_t)b * S + q) * S;
    const int tid = threadIdx.x;

    __shared__ float red[256];

    float vals[8];
#pragma unroll
    for (int i = 0; i < 8; i++) vals[i] = row[tid + i * 256];

    float lmax = -INFINITY;
#pragma unroll
    for (int i = 0; i < 8; i++) lmax = fmaxf(lmax, vals[i]);
    red[tid] = lmax;
    __syncthreads();
    for (int st = 128; st > 0; st >>= 1) {
        if (tid < st) red[tid] = fmaxf(red[tid], red[tid + st]);
        __syncthreads();
    }
    const float mx = red[0];
    __syncthreads();

    float lsum = 0.0f;
#pragma unroll
    for (int i = 0; i < 8; i++) { vals[i] = expf(vals[i] - mx); lsum += vals[i]; }
    red[tid] = lsum;
    __syncthreads();
    for (int st = 128; st > 0; st >>= 1) {
        if (tid < st) red[tid] += red[tid + st];
        __syncthreads();
    }
    const float inv = 1.0f / red[0];

#pragma unroll
    for (int i = 0; i < 8; i++) {
        float p = vals[i] * inv;
        __nv_bfloat16 h, l;
        split2(p, h, l);
        oh[tid + i * 256] = h;
        ol[tid + i * 256] = l;
    }
}

// ───────────────────────── host launch ───────────────────────────────
extern "C" void kernel_launch(void* const* d_in, const int* in_sizes, int n_in,
                              void* d_out, int out_size)
{
    const float* x    = (const float*)d_in[0];
    const int*   mask = (const int*)  d_in[1];
    const float* Wq   = (const float*)d_in[2];
    const float* bq   = (const float*)d_in[3];
    const float* Wk   = (const float*)d_in[4];
    const float* bk   = (const float*)d_in[5];
    const float* Wv   = (const float*)d_in[6];
    const float* bv   = (const float*)d_in[7];
    float* out = (float*)d_out;

    cudaFuncSetAttribute(gemm_kernel<0>, cudaFuncAttributeMaxDynamicSharedMemorySize, SMEM_TOTAL);
    cudaFuncSetAttribute(gemm_kernel<1>, cudaFuncAttributeMaxDynamicSharedMemorySize, SMEM_TOTAL);
    cudaFuncSetAttribute(gemm_kernel<2>, cudaFuncAttributeMaxDynamicSharedMemorySize, SMEM_TOTAL);
    cudaFuncSetAttribute(gemm_kernel<3>, cudaFuncAttributeMaxDynamicSharedMemorySize, SMEM_TOTAL);
    cudaFuncSetAttribute(gemm_kernel<4>, cudaFuncAttributeMaxDynamicSharedMemorySize, SMEM_TOTAL);

    // 1) fp32 -> hi/lo bf16 planes
    convert_x_kernel<<<(unsigned)((size_t)Bsz * S * E / 4 / 256), 256>>>(x);
    convert_w_kernel<<<dim3(D / 32, E / 32, 3), 256>>>(Wq, Wk, Wv);

    // 2) projections: Q, K ([token][d]), V (transposed, [b][d][s])
    gemm_kernel<0><<<dim3(D / BN, (Bsz * S) / BM, 1), NTH, SMEM_TOTAL>>>(bq, nullptr, nullptr);
    gemm_kernel<1><<<dim3(D / BN, (Bsz * S) / BM, 1), NTH, SMEM_TOTAL>>>(bk, nullptr, nullptr);
    gemm_kernel<2><<<dim3((Bsz * S) / BN, D / BM, 1), NTH, SMEM_TOTAL>>>(bv, nullptr, nullptr);

    // 3) scores = QK^T / 1024, masked
    gemm_kernel<3><<<dim3(S / BN, S / BM, Bsz), NTH, SMEM_TOTAL>>>(nullptr, mask, nullptr);

    // 4) softmax -> prob planes
    softmax_kernel<<<dim3(S, Bsz), 256>>>();

    // 5) out = P @ V
    gemm_kernel<4><<<dim3(D / BN, S / BM, Bsz), NTH, SMEM_TOTAL>>>(nullptr, nullptr, out);
}